// round 4
// baseline (speedup 1.0000x reference)
#include <cuda_runtime.h>
#include <math.h>

#define BATCH 8
#define SEQ   4096
#define DIM   1024
#define VOCAB 50257
#define CHUNK  64
#define NCHUNK 64   /* CHUNK*NCHUNK == SEQ */

// Decoder tiling
#define RPB     64                    /* vocab rows per block   */
#define KCH     64                    /* k floats per stage     */
#define NKCH    (DIM / KCH)           /* 16 k-chunks            */
#define NSTAGES 3
#define STAGE_F (RPB * KCH)           /* 4096 floats = 16 KB    */
#define SMEM_DEC ((BATCH * DIM + NSTAGES * STAGE_F) * 4)   /* 80 KB */

// Scratch (allocation-free rule: __device__ globals)
__device__ float g_hpart[NCHUNK * BATCH * DIM];
__device__ float g_h [BATCH * DIM];
__device__ float g_V [BATCH * DIM];   // tanh(h)
__device__ float g_Hc[BATCH * DIM];
__device__ float g_Vp[BATCH * DIM];

__device__ __forceinline__ float sigmoidf_(float x) { return 1.0f / (1.0f + expf(-x)); }

__device__ __forceinline__ void ffma2(unsigned long long& a,
                                      unsigned long long w,
                                      unsigned long long v)
{
    asm("fma.rn.f32x2 %0, %1, %2, %0;" : "+l"(a) : "l"(w), "l"(v));
}
__device__ __forceinline__ float unpack_sum(unsigned long long a)
{
    float lo, hi;
    asm("mov.b64 {%0, %1}, %2;" : "=f"(lo), "=f"(hi) : "l"(a));
    return lo + hi;
}

// ---------------------------------------------------------------------------
// Kernel A: EMA as truncated geometric weighted sum, chunked backward in time.
// ---------------------------------------------------------------------------
__global__ __launch_bounds__(256) void ema_chunk_kernel(
    const int*   __restrict__ ids,
    const float* __restrict__ emb,
    const float* __restrict__ enc_decay)
{
    const int chunk = blockIdx.x;
    const int b     = blockIdx.y;
    const int t4    = threadIdx.x;

    __shared__ int sids[CHUNK];
    if (threadIdx.x < CHUNK) {
        int k = chunk * CHUNK + threadIdx.x;
        sids[threadIdx.x] = ids[b * SEQ + (SEQ - 1 - k)];
    }

    float4 ed = ((const float4*)enc_decay)[t4];
    float dx = sigmoidf_(ed.x), dy = sigmoidf_(ed.y);
    float dz = sigmoidf_(ed.z), dw = sigmoidf_(ed.w);

    float fk0 = (float)(chunk * CHUNK);
    float px = powf(dx, fk0), py = powf(dy, fk0);
    float pz = powf(dz, fk0), pw = powf(dw, fk0);

    __syncthreads();

    float4 acc = make_float4(0.f, 0.f, 0.f, 0.f);
    float pmax = fmaxf(fmaxf(px, py), fmaxf(pz, pw));
    if (pmax > 1e-7f) {
        float wx = (1.0f - dx) * px, wy = (1.0f - dy) * py;
        float wz = (1.0f - dz) * pz, ww = (1.0f - dw) * pw;
        #pragma unroll 8
        for (int i = 0; i < CHUNK; i++) {
            const float4 x = __ldg((const float4*)emb + (size_t)sids[i] * (DIM / 4) + t4);
            acc.x += wx * x.x;  acc.y += wy * x.y;
            acc.z += wz * x.z;  acc.w += ww * x.w;
            wx *= dx; wy *= dy; wz *= dz; ww *= dw;
        }
    }
    ((float4*)g_hpart)[((size_t)chunk * BATCH + b) * (DIM / 4) + t4] = acc;
}

// ---------------------------------------------------------------------------
// Kernel R: fixed-order reduction of chunk partials -> g_h, g_V = tanh(g_h)
// ---------------------------------------------------------------------------
__global__ __launch_bounds__(256) void reduce_h_kernel()
{
    int e = blockIdx.x * 256 + threadIdx.x;
    const float4* hp = (const float4*)g_hpart;
    float4 s = make_float4(0.f, 0.f, 0.f, 0.f);
    #pragma unroll 8
    for (int c = 0; c < NCHUNK; c++) {
        float4 v = hp[(size_t)c * (BATCH * DIM / 4) + e];
        s.x += v.x; s.y += v.y; s.z += v.z; s.w += v.w;
    }
    ((float4*)g_h)[e] = s;
    float4 t = make_float4(tanhf(s.x), tanhf(s.y), tanhf(s.z), tanhf(s.w));
    ((float4*)g_V)[e] = t;
}

// ---------------------------------------------------------------------------
// Kernel B: small dense (8 x 1024 x 1024), warp-per-output, 256 blocks x 128.
// Activations read straight from global (L2-hot broadcast), no smem stage.
// MODE 0: in = g_V, out: g_Hc = sigmoid(cry)*h + sigmoid(V@Wg^T+bg)*V
// MODE 1: in = g_Hc, out: g_Vp = tanh(Hc@Wc^T + cb)
// ---------------------------------------------------------------------------
template <int MODE>
__global__ __launch_bounds__(128) void dense_kernel(
    const float* __restrict__ W,
    const float* __restrict__ bias,
    const float* __restrict__ cry_decay)
{
    const int lane = threadIdx.x & 31;
    const int o    = blockIdx.x * 4 + (threadIdx.x >> 5);

    const float4* act4 = (const float4*)(MODE == 0 ? g_V : g_Hc);
    const float4* Wrow = (const float4*)W + (size_t)o * (DIM / 4);

    float acc[BATCH];
    #pragma unroll
    for (int b = 0; b < BATCH; b++) acc[b] = 0.f;

    #pragma unroll
    for (int i = 0; i < 8; i++) {
        float4 w4 = __ldg(Wrow + i * 32 + lane);
        #pragma unroll
        for (int b = 0; b < BATCH; b++) {
            float4 v4 = __ldg(act4 + b * 256 + i * 32 + lane);
            acc[b] += w4.x * v4.x + w4.y * v4.y + w4.z * v4.z + w4.w * v4.w;
        }
    }
    #pragma unroll
    for (int b = 0; b < BATCH; b++)
        #pragma unroll
        for (int off = 16; off; off >>= 1)
            acc[b] += __shfl_xor_sync(0xffffffffu, acc[b], off);

    if (lane < BATCH) {
        const int b = lane;
        float dot = acc[b] + bias[o];
        if (MODE == 0) {
            float g  = sigmoidf_(dot);
            float cd = sigmoidf_(cry_decay[o]);
            g_Hc[b * DIM + o] = cd * g_h[b * DIM + o] + g * g_V[b * DIM + o];
        } else {
            g_Vp[b * DIM + o] = tanhf(dot);
        }
    }
}

// ---------------------------------------------------------------------------
// Kernel C: decoder, cp.async pipelined.
// Block: 256 thr, 64 vocab rows. W streamed as 3-stage ring of 64x64 tiles.
// Warp = 8 rows; lane = (half:rows 4, i:k-quad 0..15). K paired into f32x2.
// Cross-lane K partials folded with a 16-lane shfl butterfly.
// ---------------------------------------------------------------------------
__device__ __forceinline__ void dec_issue_stage(
    float* sw, int c, int row0, int tid, const float* __restrict__ dW)
{
    float* dst = sw + (c % NSTAGES) * STAGE_F;
    #pragma unroll
    for (int q = 0; q < 4; q++) {
        int seg = q * 256 + tid;        // 0..1023 (16B units of the tile)
        int r   = seg >> 4;             // tile row
        int col = seg & 15;             // 16B column within the 256B row-chunk
        int rowg = min(row0 + r, VOCAB - 1);
        const float* src = dW + (size_t)rowg * DIM + c * KCH + col * 4;
        unsigned daddr = (unsigned)__cvta_generic_to_shared(dst + seg * 4);
        asm volatile("cp.async.cg.shared.global [%0], [%1], 16;\n"
                     :: "r"(daddr), "l"(src));
    }
    asm volatile("cp.async.commit_group;\n");
}

__global__ __launch_bounds__(256, 2) void decoder_kernel(
    const float* __restrict__ dec_W,
    const float* __restrict__ dec_b,
    float*       __restrict__ out)
{
    extern __shared__ float smem[];
    float* sv = smem;                       // activations, 8192 f32
    float* sw = smem + BATCH * DIM;         // W ring, 3 x 4096 f32

    const int tid  = threadIdx.x;
    const int w    = tid >> 5;
    const int lane = tid & 31;
    const int half = lane >> 4;
    const int i    = lane & 15;
    const int row0 = blockIdx.x * RPB;

    // Stage activations (once)
    {
        const float4* vp4 = (const float4*)g_Vp;
        float4* sv4 = (float4*)sv;
        #pragma unroll
        for (int q = 0; q < 8; q++) sv4[q * 256 + tid] = __ldg(vp4 + q * 256 + tid);
    }

    dec_issue_stage(sw, 0, row0, tid, dec_W);
    dec_issue_stage(sw, 1, row0, tid, dec_W);

    unsigned long long acc[4][BATCH];
    #pragma unroll
    for (int r = 0; r < 4; r++)
        #pragma unroll
        for (int b = 0; b < BATCH; b++) acc[r][b] = 0ull;

    const int wrow = w * 8 + half * 4;     // this lane's first tile row

    for (int c = 0; c < NKCH; c++) {
        if (c + 2 < NKCH) dec_issue_stage(sw, c + 2, row0, tid, dec_W);
        else              asm volatile("cp.async.commit_group;\n");  // keep group count uniform
        asm volatile("cp.async.wait_group 2;\n");
        __syncthreads();

        const float4* wt4 = (const float4*)(sw + (c % NSTAGES) * STAGE_F);
        const float4* sv4 = (const float4*)sv;

        unsigned long long wlo[4], whi[4];
        #pragma unroll
        for (int r = 0; r < 4; r++) {
            float4 f = wt4[(wrow + r) * 16 + i];
            ulonglong2 u = *reinterpret_cast<ulonglong2*>(&f);
            wlo[r] = u.x; whi[r] = u.y;
        }
        #pragma unroll
        for (int b = 0; b < BATCH; b++) {
            float4 v = sv4[b * 256 + c * 16 + i];
            ulonglong2 uv = *reinterpret_cast<ulonglong2*>(&v);
            #pragma unroll
            for (int r = 0; r < 4; r++) {
                ffma2(acc[r][b], wlo[r], uv.x);
                ffma2(acc[r][b], whi[r], uv.y);
            }
        }
        __syncthreads();    // stage consumed; safe to overwrite next iter
    }

    // Fold packed halves, then butterfly over the 16-lane k-split group
    float f[4][BATCH];
    #pragma unroll
    for (int r = 0; r < 4; r++)
        #pragma unroll
        for (int b = 0; b < BATCH; b++) f[r][b] = unpack_sum(acc[r][b]);

    #pragma unroll
    for (int off = 1; off < 16; off <<= 1)
        #pragma unroll
        for (int r = 0; r < 4; r++)
            #pragma unroll
            for (int b = 0; b < BATCH; b++)
                f[r][b] += __shfl_xor_sync(0xffffffffu, f[r][b], off);

    if ((lane & 15) < 8) {
        const int b  = lane & 7;
        const int rb = row0 + wrow;
        #pragma unroll
        for (int r = 0; r < 4; r++) {
            int v = rb + r;
            if (v < VOCAB)
                out[(size_t)b * VOCAB + v] = f[r][b] + __ldg(dec_b + v);
        }
    }
}

// ---------------------------------------------------------------------------
extern "C" void kernel_launch(void* const* d_in, const int* in_sizes, int n_in,
                              void* d_out, int out_size)
{
    (void)in_sizes; (void)n_in; (void)out_size;
    const int*   ids = (const int*)  d_in[0];
    const float* emb = (const float*)d_in[1];
    const float* enc = (const float*)d_in[2];
    const float* cry = (const float*)d_in[3];
    const float* gW  = (const float*)d_in[4];
    const float* gb  = (const float*)d_in[5];
    const float* cW  = (const float*)d_in[6];
    const float* cb  = (const float*)d_in[7];
    const float* dW  = (const float*)d_in[8];
    const float* db  = (const float*)d_in[9];
    float* out = (float*)d_out;

    cudaFuncSetAttribute(decoder_kernel,
                         cudaFuncAttributeMaxDynamicSharedMemorySize, SMEM_DEC);

    ema_chunk_kernel<<<dim3(NCHUNK, BATCH), 256>>>(ids, emb, enc);
    reduce_h_kernel<<<(BATCH * DIM / 4) / 256, 256>>>();
    dense_kernel<0><<<DIM / 4, 128>>>(gW, gb, cry);
    dense_kernel<1><<<DIM / 4, 128>>>(cW, cb, nullptr);
    decoder_kernel<<<(VOCAB + RPB - 1) / RPB, 256, SMEM_DEC>>>(dW, db, out);
}

// round 6
// speedup vs baseline: 1.1632x; 1.1632x over previous
#include <cuda_runtime.h>
#include <math.h>

#define BATCH 8
#define SEQ   4096
#define DIM   1024
#define VOCAB 50257
#define CHUNK  64
#define NCHUNK 64   /* CHUNK*NCHUNK == SEQ */

// Decoder tiling
#define RPB     64                     /* vocab rows per tile          */
#define KCH     64                     /* k floats per stage           */
#define NKCH    (DIM / KCH)            /* 16 k-chunks per tile         */
#define NSTAGES 4
#define STAGE_F (RPB * KCH)            /* 4096 floats = 16 KB          */
#define GRIDC   296                    /* persistent blocks (2 per SM) */
#define NTILES  ((VOCAB + RPB - 1) / RPB)   /* 786                     */
#define SMEM_DEC ((BATCH * DIM + NSTAGES * STAGE_F) * 4)   /* 96 KB   */

// Scratch (allocation-free rule: __device__ globals)
__device__ float g_hpart[NCHUNK * BATCH * DIM];
__device__ float g_h [BATCH * DIM];
__device__ float g_V [BATCH * DIM];   // tanh(h)
__device__ float g_Hc[BATCH * DIM];
__device__ float g_Vp[BATCH * DIM];

__device__ __forceinline__ float sigmoidf_(float x) { return 1.0f / (1.0f + expf(-x)); }

__device__ __forceinline__ void ffma2(unsigned long long& a,
                                      unsigned long long w,
                                      unsigned long long v)
{
    asm("fma.rn.f32x2 %0, %1, %2, %0;" : "+l"(a) : "l"(w), "l"(v));
}
__device__ __forceinline__ float unpack_sum(unsigned long long a)
{
    float lo, hi;
    asm("mov.b64 {%0, %1}, %2;" : "=f"(lo), "=f"(hi) : "l"(a));
    return lo + hi;
}

// ---------------------------------------------------------------------------
// Kernel A: EMA as truncated geometric weighted sum, chunked backward in time.
// ---------------------------------------------------------------------------
__global__ __launch_bounds__(256) void ema_chunk_kernel(
    const int*   __restrict__ ids,
    const float* __restrict__ emb,
    const float* __restrict__ enc_decay)
{
    const int chunk = blockIdx.x;
    const int b     = blockIdx.y;
    const int t4    = threadIdx.x;

    __shared__ int sids[CHUNK];
    if (threadIdx.x < CHUNK) {
        int k = chunk * CHUNK + threadIdx.x;
        sids[threadIdx.x] = ids[b * SEQ + (SEQ - 1 - k)];
    }

    float4 ed = ((const float4*)enc_decay)[t4];
    float dx = sigmoidf_(ed.x), dy = sigmoidf_(ed.y);
    float dz = sigmoidf_(ed.z), dw = sigmoidf_(ed.w);

    float fk0 = (float)(chunk * CHUNK);
    float px = powf(dx, fk0), py = powf(dy, fk0);
    float pz = powf(dz, fk0), pw = powf(dw, fk0);

    __syncthreads();

    float4 acc = make_float4(0.f, 0.f, 0.f, 0.f);
    float pmax = fmaxf(fmaxf(px, py), fmaxf(pz, pw));
    if (pmax > 1e-7f) {
        float wx = (1.0f - dx) * px, wy = (1.0f - dy) * py;
        float wz = (1.0f - dz) * pz, ww = (1.0f - dw) * pw;
        #pragma unroll 8
        for (int i = 0; i < CHUNK; i++) {
            const float4 x = __ldg((const float4*)emb + (size_t)sids[i] * (DIM / 4) + t4);
            acc.x += wx * x.x;  acc.y += wy * x.y;
            acc.z += wz * x.z;  acc.w += ww * x.w;
            wx *= dx; wy *= dy; wz *= dz; ww *= dw;
        }
    }
    ((float4*)g_hpart)[((size_t)chunk * BATCH + b) * (DIM / 4) + t4] = acc;
}

// ---------------------------------------------------------------------------
// Kernel R: fixed-order reduction of chunk partials -> g_h, g_V = tanh(g_h)
// ---------------------------------------------------------------------------
__global__ __launch_bounds__(256) void reduce_h_kernel()
{
    int e = blockIdx.x * 256 + threadIdx.x;
    const float4* hp = (const float4*)g_hpart;
    float4 s = make_float4(0.f, 0.f, 0.f, 0.f);
    #pragma unroll 8
    for (int c = 0; c < NCHUNK; c++) {
        float4 v = hp[(size_t)c * (BATCH * DIM / 4) + e];
        s.x += v.x; s.y += v.y; s.z += v.z; s.w += v.w;
    }
    ((float4*)g_h)[e] = s;
    float4 t = make_float4(tanhf(s.x), tanhf(s.y), tanhf(s.z), tanhf(s.w));
    ((float4*)g_V)[e] = t;
}

// ---------------------------------------------------------------------------
// Kernel B: small dense (8 x 1024 x 1024), K-split: one output per block,
// 4 warps each own a K-quarter (256 floats), smem cross-warp fold.
// 1024 blocks x 128 thr -> 4096 warps chip-wide (latency hidden by warps).
// MODE 0: in = g_V, out: g_Hc = sigmoid(cry)*h + sigmoid(V@Wg^T+bg)*V
// MODE 1: in = g_Hc, out: g_Vp = tanh(Hc@Wc^T + cb)
// ---------------------------------------------------------------------------
template <int MODE>
__global__ __launch_bounds__(128) void dense_kernel(
    const float* __restrict__ W,
    const float* __restrict__ bias,
    const float* __restrict__ cry_decay)
{
    const int o    = blockIdx.x;
    const int w    = threadIdx.x >> 5;
    const int lane = threadIdx.x & 31;

    const float4* act4 = (const float4*)(MODE == 0 ? g_V : g_Hc);
    const float4* Wrow = (const float4*)W + (size_t)o * (DIM / 4);

    float acc[BATCH];
    #pragma unroll
    for (int b = 0; b < BATCH; b++) acc[b] = 0.f;

    #pragma unroll
    for (int j = 0; j < 2; j++) {
        const int k4 = w * 64 + j * 32 + lane;      // float4 index in [0,256)
        float4 w4 = __ldg(Wrow + k4);
        #pragma unroll
        for (int b = 0; b < BATCH; b++) {
            float4 v4 = __ldg(act4 + b * 256 + k4);
            acc[b] += w4.x * v4.x + w4.y * v4.y + w4.z * v4.z + w4.w * v4.w;
        }
    }
    #pragma unroll
    for (int b = 0; b < BATCH; b++)
        #pragma unroll
        for (int off = 16; off; off >>= 1)
            acc[b] += __shfl_xor_sync(0xffffffffu, acc[b], off);

    __shared__ float part[4][BATCH];
    if (lane == 0) {
        #pragma unroll
        for (int b = 0; b < BATCH; b++) part[w][b] = acc[b];
    }
    __syncthreads();

    if (threadIdx.x < BATCH) {
        const int b = threadIdx.x;
        float dot = part[0][b] + part[1][b] + part[2][b] + part[3][b] + bias[o];
        if (MODE == 0) {
            float g  = sigmoidf_(dot);
            float cd = sigmoidf_(cry_decay[o]);
            g_Hc[b * DIM + o] = cd * g_h[b * DIM + o] + g * g_V[b * DIM + o];
        } else {
            g_Vp[b * DIM + o] = tanhf(dot);
        }
    }
}

// ---------------------------------------------------------------------------
// Kernel C: decoder, persistent blocks + 4-stage cp.async ring running
// continuously across row-tiles; ONE __syncthreads per k-chunk.
// Block: 256 thr. Tile = 64 vocab rows. Warp = 8 rows; lane = (half: 4 rows,
// i: k-quad 0..15). K paired into f32x2; 16-lane shfl butterfly at tile end.
// ---------------------------------------------------------------------------
__device__ __forceinline__ void dec_issue_stage(
    float* sw, int gc, int bid, int tid, const float* __restrict__ dW)
{
    const int slot = gc & (NSTAGES - 1);
    const int c    = gc & (NKCH - 1);
    const int row0 = (bid + (gc >> 4) * GRIDC) * RPB;
    float* dst = sw + slot * STAGE_F;
    #pragma unroll
    for (int q = 0; q < 4; q++) {
        int seg = q * 256 + tid;        // 0..1023 (16B units of the tile)
        int r   = seg >> 4;             // tile row
        int col = seg & 15;             // 16B column
        int rowg = min(row0 + r, VOCAB - 1);
        const float* src = dW + (size_t)rowg * DIM + c * KCH + col * 4;
        unsigned daddr = (unsigned)__cvta_generic_to_shared(dst + seg * 4);
        asm volatile("cp.async.cg.shared.global [%0], [%1], 16;\n"
                     :: "r"(daddr), "l"(src));
    }
    asm volatile("cp.async.commit_group;\n");
}

__global__ __launch_bounds__(256, 2) void decoder_kernel(
    const float* __restrict__ dec_W,
    const float* __restrict__ dec_b,
    float*       __restrict__ out)
{
    extern __shared__ float smem[];
    float* sv = smem;                       // activations, 8192 f32
    float* sw = smem + BATCH * DIM;         // W ring, 4 x 4096 f32

    const int tid  = threadIdx.x;
    const int w    = tid >> 5;
    const int lane = tid & 31;
    const int half = lane >> 4;
    const int i    = lane & 15;
    const int bid  = blockIdx.x;

    // Stage activations once per (persistent) block
    {
        const float4* vp4 = (const float4*)g_Vp;
        float4* sv4 = (float4*)sv;
        #pragma unroll
        for (int q = 0; q < 8; q++) sv4[q * 256 + tid] = __ldg(vp4 + q * 256 + tid);
    }

    int ntiles = 0;
    for (int t = bid; t < NTILES; t += GRIDC) ntiles++;
    const int total = ntiles * NKCH;        // >= 32 (every block has >= 2 tiles)

    dec_issue_stage(sw, 0, bid, tid, dec_W);
    dec_issue_stage(sw, 1, bid, tid, dec_W);
    dec_issue_stage(sw, 2, bid, tid, dec_W);

    unsigned long long acc[4][BATCH];
    #pragma unroll
    for (int r = 0; r < 4; r++)
        #pragma unroll
        for (int b = 0; b < BATCH; b++) acc[r][b] = 0ull;

    const int wrow = w * 8 + half * 4;      // this lane's first tile row

    for (int gc = 0; gc < total; gc++) {
        asm volatile("cp.async.wait_group 2;\n");
        __syncthreads();   // stage gc ready+visible; all done reading stage gc-1
        if (gc + 3 < total) dec_issue_stage(sw, gc + 3, bid, tid, dec_W);
        else                asm volatile("cp.async.commit_group;\n");

        const int c = gc & (NKCH - 1);
        const float4* wt4 = (const float4*)(sw + (gc & (NSTAGES - 1)) * STAGE_F);
        const float4* sv4 = (const float4*)sv;

        unsigned long long wlo[4], whi[4];
        #pragma unroll
        for (int r = 0; r < 4; r++) {
            float4 f = wt4[(wrow + r) * 16 + i];
            ulonglong2 u = *reinterpret_cast<ulonglong2*>(&f);
            wlo[r] = u.x; whi[r] = u.y;
        }
        #pragma unroll
        for (int b = 0; b < BATCH; b++) {
            float4 v = sv4[b * 256 + c * 16 + i];
            ulonglong2 uv = *reinterpret_cast<ulonglong2*>(&v);
            #pragma unroll
            for (int r = 0; r < 4; r++) {
                ffma2(acc[r][b], wlo[r], uv.x);
                ffma2(acc[r][b], whi[r], uv.y);
            }
        }

        if (c == NKCH - 1) {
            // Tile finished: fold packed halves + 16-lane butterfly, write out.
            const int row0 = (bid + (gc >> 4) * GRIDC) * RPB;
            float f[4][BATCH];
            #pragma unroll
            for (int r = 0; r < 4; r++)
                #pragma unroll
                for (int b = 0; b < BATCH; b++) {
                    f[r][b] = unpack_sum(acc[r][b]);
                    acc[r][b] = 0ull;
                }
            #pragma unroll
            for (int off = 1; off < 16; off <<= 1)
                #pragma unroll
                for (int r = 0; r < 4; r++)
                    #pragma unroll
                    for (int b = 0; b < BATCH; b++)
                        f[r][b] += __shfl_xor_sync(0xffffffffu, f[r][b], off);

            if (i < 8) {
                const int b  = i;
                const int rb = row0 + wrow;
                #pragma unroll
                for (int r = 0; r < 4; r++) {
                    int v = rb + r;
                    if (v < VOCAB)
                        out[(size_t)b * VOCAB + v] = f[r][b] + __ldg(dec_b + v);
                }
            }
        }
    }
}

// ---------------------------------------------------------------------------
extern "C" void kernel_launch(void* const* d_in, const int* in_sizes, int n_in,
                              void* d_out, int out_size)
{
    (void)in_sizes; (void)n_in; (void)out_size;
    const int*   ids = (const int*)  d_in[0];
    const float* emb = (const float*)d_in[1];
    const float* enc = (const float*)d_in[2];
    const float* cry = (const float*)d_in[3];
    const float* gW  = (const float*)d_in[4];
    const float* gb  = (const float*)d_in[5];
    const float* cW  = (const float*)d_in[6];
    const float* cb  = (const float*)d_in[7];
    const float* dW  = (const float*)d_in[8];
    const float* db  = (const float*)d_in[9];
    float* out = (float*)d_out;

    cudaFuncSetAttribute(decoder_kernel,
                         cudaFuncAttributeMaxDynamicSharedMemorySize, SMEM_DEC);

    ema_chunk_kernel<<<dim3(NCHUNK, BATCH), 256>>>(ids, emb, enc);
    reduce_h_kernel<<<(BATCH * DIM / 4) / 256, 256>>>();
    dense_kernel<0><<<DIM, 128>>>(gW, gb, cry);
    dense_kernel<1><<<DIM, 128>>>(cW, cb, nullptr);
    decoder_kernel<<<GRIDC, 256, SMEM_DEC>>>(dW, db, out);
}